// round 16
// baseline (speedup 1.0000x reference)
#include <cuda_runtime.h>
#include <math.h>

#define NN 50000
#define EE 800000
#define INC 64
#define HC 128
#define C1N 64
#define C2N 16
#define LN_EPS 1e-5f
#define THRESH1 (1.0f/63.0f)

typedef unsigned long long u64;
typedef unsigned int u32;

// ---------------- device scratch ----------------
__device__ __align__(16) float d_agg[NN*INC];
__device__ __align__(16) float d_x1[NN*HC];
__device__ __align__(16) float d_s[NN*C1N];
__device__ __align__(16) float d_As[NN*C1N];
__device__ __align__(16) float d_pooled[C1N*256];
__device__ float d_den;
__device__ __align__(16) float d_Wcat[HC*HC];    // [k][h]
__device__ __align__(16) float d_pW1t[HC*C1N];   // [k][c]
__device__ __align__(16) float d_W2relT[HC*HC];  // [f][h]
__device__ __align__(16) float d_W2rootT[HC*HC]; // [f][h]
__device__ __align__(16) float d_pW2t[HC*C2N];   // [h][c]

__device__ __forceinline__ void red_add4(float* addr, float4 v) {
    asm volatile("red.global.add.v4.f32 [%0], {%1,%2,%3,%4};"
                 :: "l"(addr), "f"(v.x), "f"(v.y), "f"(v.z), "f"(v.w) : "memory");
}
__device__ __forceinline__ u64 dup2(float a) {
    u64 r; asm("mov.b64 %0, {%1, %1};" : "=l"(r) : "f"(a)); return r;
}
__device__ __forceinline__ void ffma2(u64& d, u64 a, u64 b) {
    asm("fma.rn.f32x2 %0, %1, %2, %0;" : "+l"(d) : "l"(a), "l"(b));
}
__device__ __forceinline__ float2 unpk(u64 v) {
    float2 r; asm("mov.b64 {%0, %1}, %2;" : "=f"(r.x), "=f"(r.y) : "l"(v)); return r;
}
__device__ __forceinline__ u64 ldg64(const float* p) {
    return __ldg((const unsigned long long*)p);
}
__device__ __forceinline__ u32 smem_u32(const void* p) {
    u32 a;
    asm("{ .reg .u64 tmp; cvta.to.shared.u64 tmp, %1; cvt.u32.u64 %0, tmp; }" : "=r"(a) : "l"(p));
    return a;
}
__device__ __forceinline__ void cp16(u32 dst, const void* src) {
    asm volatile("cp.async.cg.shared.global [%0], [%1], 16;" :: "r"(dst), "l"(src));
}

// ---------------- kinitA: zero d_agg only (gates scatter1) ----------------
__global__ void kinitA() {
    int i0 = blockIdx.x*blockDim.x + threadIdx.x, st = gridDim.x*blockDim.x;
    float4 z = make_float4(0.f,0.f,0.f,0.f);
    for (int i = i0; i < NN*INC/4; i += st) ((float4*)d_agg)[i] = z;
}

// ---------------- kmerge0: scatter1 (blocks 0..4095) + initB (4096..4351) ----------------
__global__ void kmerge0(const float* __restrict__ x, const float* __restrict__ dm,
                        const int* __restrict__ row, const int* __restrict__ col,
                        const float* __restrict__ W1rel, const float* __restrict__ W1root,
                        const float* __restrict__ pW1,
                        const float* __restrict__ W2rel, const float* __restrict__ W2root,
                        const float* __restrict__ pW2) {
    if (blockIdx.x < 4096) {
        int i0 = blockIdx.x*256 + threadIdx.x, st = 4096*256;
        for (int i = i0; i < EE*16; i += st) {
            int e = i >> 4, c = i & 15;
            int r = row[e];
            float m = dm[r];
            if (m != 0.0f) {
                int d = col[e];
                float4 v = ((const float4*)(x + (size_t)r*INC))[c];
                v.x *= m; v.y *= m; v.z *= m; v.w *= m;
                red_add4((float*)(((float4*)(d_agg + (size_t)d*INC)) + c), v);
            }
        }
    } else {
        int j0 = (blockIdx.x - 4096)*256 + threadIdx.x, st = 256*256;
        float4 z = make_float4(0.f,0.f,0.f,0.f);
        for (int i = j0; i < NN*INC/4; i += st) ((float4*)d_As)[i] = z;
        for (int i = j0; i < C1N*64;   i += st) ((float4*)d_pooled)[i] = z;
        if (j0 == 0) d_den = 0.f;
        for (int i = j0; i < HC*HC; i += st) {
            int k = i >> 7, h = i & 127;
            d_Wcat[i] = (k < 64) ? W1rel[h*64 + k] : W1root[h*64 + (k - 64)];
            d_W2relT[i]  = W2rel[h*128 + k];
            d_W2rootT[i] = W2root[h*128 + k];
        }
        for (int i = j0; i < HC*C1N; i += st) {
            int k = i >> 6, c = i & 63;
            d_pW1t[i] = pW1[c*128 + k];
        }
        for (int i = j0; i < HC*C2N; i += st) {
            int h = i >> 4, c = i & 15;
            d_pW2t[i] = pW2[c*128 + h];
        }
    }
}

// ---------------- kAB: fused X1 + s1 pipeline (unchanged from R15) ----------------
#define KAB_OVL_FLOATS (64*68)
#define KAB_SMEM_FLOATS (128*68 + KAB_OVL_FLOATS + 192)
#define KAB_SMEM_BYTES  (KAB_SMEM_FLOATS*4)

__global__ void __launch_bounds__(128, 4) kAB(const float* __restrict__ x,
                                              const float* __restrict__ dm,
                                              const float* __restrict__ b1,
                                              const float* __restrict__ pb1,
                                              const float* __restrict__ g1,
                                              const float* __restrict__ be1,
                                              float* __restrict__ ls1out) {
    extern __shared__ float sm[];
    float* As   = sm;
    float* ovl  = As + 128*68;
    float* pb1s = ovl + KAB_OVL_FLOATS;
    float* g1s  = pb1s + 64;
    float* be1s = g1s + 64;
    float* s1S  = ovl;

    int t = threadIdx.x;
    u32 ovl_u32 = smem_u32(ovl);

    #pragma unroll
    for (int p = 0; p < 4; p++) {
        int f4 = t + 128*p;
        cp16(ovl_u32 + f4*16, d_Wcat + f4*4);
    }
    asm volatile("cp.async.commit_group;" ::: "memory");

    if (t < 64) { pb1s[t] = pb1[t]; g1s[t] = g1[t]; be1s[t] = be1[t]; }

    int nb = blockIdx.x * 64;
    {
        int m = t & 63, grp = t >> 6;
        int node = nb + m;
        bool valid = node < NN;
        float dmn = valid ? dm[node] : 0.f;
        for (int q = grp; q < 32; q += 2) {
            float4 v;
            if (valid) {
                if (q < 16) v = ((const float4*)(d_agg + (size_t)node*INC))[q];
                else {
                    v = ((const float4*)(x + (size_t)node*INC))[q - 16];
                    v.x *= dmn; v.y *= dmn; v.z *= dmn; v.w *= dmn;
                }
            } else v = make_float4(0.f, 0.f, 0.f, 0.f);
            int k0 = q * 4;
            As[(k0+0)*68 + m] = v.x;
            As[(k0+1)*68 + m] = v.y;
            As[(k0+2)*68 + m] = v.z;
            As[(k0+3)*68 + m] = v.w;
        }
    }

    int tx = t & 15, ty = t >> 4;
    {
        u64 acc[8][4];
        #pragma unroll
        for (int i = 0; i < 8; i++) { acc[i][0]=0; acc[i][1]=0; acc[i][2]=0; acc[i][3]=0; }

        for (int c = 0; c < 8; c++) {
            asm volatile("cp.async.wait_group 0;" ::: "memory");
            __syncthreads();
            if (c < 7) {
                const float* src = d_Wcat + (c+1)*2048;
                u32 dst = ovl_u32 + ((c+1) & 1)*2048*4;
                #pragma unroll
                for (int p = 0; p < 4; p++) {
                    int f4 = t + 128*p;
                    cp16(dst + f4*16, src + f4*4);
                }
                asm volatile("cp.async.commit_group;" ::: "memory");
            }
            const float* Wb = ovl + (c & 1)*2048;
            #pragma unroll
            for (int kk = 0; kk < 16; kk++) {
                int k = c*16 + kk;
                const float* ap = As + k*68 + ty*8;
                float4 aA = *(const float4*)ap;
                float4 aB = *(const float4*)(ap + 4);
                const u64* wr = (const u64*)(Wb + kk*128);
                u64 w0 = wr[tx], w1 = wr[tx+16], w2 = wr[tx+32], w3 = wr[tx+48];
                float av[8] = {aA.x, aA.y, aA.z, aA.w, aB.x, aB.y, aB.z, aB.w};
                #pragma unroll
                for (int i = 0; i < 8; i++) {
                    u64 Ai = dup2(av[i]);
                    ffma2(acc[i][0], Ai, w0);
                    ffma2(acc[i][1], Ai, w1);
                    ffma2(acc[i][2], Ai, w2);
                    ffma2(acc[i][3], Ai, w3);
                }
            }
        }
        __syncthreads();

        float bb[8];
        #pragma unroll
        for (int j = 0; j < 4; j++) { bb[2*j] = b1[2*tx + 32*j]; bb[2*j+1] = b1[2*tx + 1 + 32*j]; }
        #pragma unroll
        for (int i = 0; i < 8; i++) {
            int m = ty*8 + i;
            int nd = nb + m;
            #pragma unroll
            for (int j = 0; j < 4; j++) {
                float2 p = unpk(acc[i][j]);
                float2 o = make_float2(fmaxf(p.x + bb[2*j], 0.f), fmaxf(p.y + bb[2*j+1], 0.f));
                int h = 2*tx + 32*j;
                As[h*68 + m]     = o.x;
                As[(h+1)*68 + m] = o.y;
                if (nd < NN) *((float2*)(d_x1 + (size_t)nd*HC + h)) = o;
            }
        }
    }
    {
        #pragma unroll
        for (int p = 0; p < 2; p++) {
            int f4 = t + 128*p;
            cp16(ovl_u32 + f4*16, d_pW1t + f4*4);
        }
        asm volatile("cp.async.commit_group;" ::: "memory");
    }

    {
        u64 acc[8][2];
        #pragma unroll
        for (int i = 0; i < 8; i++) { acc[i][0]=0; acc[i][1]=0; }

        for (int c = 0; c < 8; c++) {
            asm volatile("cp.async.wait_group 0;" ::: "memory");
            __syncthreads();
            if (c < 7) {
                const float* src = d_pW1t + (c+1)*1024;
                u32 dst = ovl_u32 + ((c+1) & 1)*1024*4;
                #pragma unroll
                for (int p = 0; p < 2; p++) {
                    int f4 = t + 128*p;
                    cp16(dst + f4*16, src + f4*4);
                }
                asm volatile("cp.async.commit_group;" ::: "memory");
            }
            const float* Wb = ovl + (c & 1)*1024;
            #pragma unroll
            for (int kk = 0; kk < 16; kk++) {
                int k = c*16 + kk;
                const float* ap = As + k*68 + ty*8;
                float4 aA = *(const float4*)ap;
                float4 aB = *(const float4*)(ap + 4);
                const u64* wr = (const u64*)(Wb + kk*64);
                u64 w0 = wr[tx], w1 = wr[tx+16];
                float av[8] = {aA.x, aA.y, aA.z, aA.w, aB.x, aB.y, aB.z, aB.w};
                #pragma unroll
                for (int i = 0; i < 8; i++) {
                    u64 Ai = dup2(av[i]);
                    ffma2(acc[i][0], Ai, w0);
                    ffma2(acc[i][1], Ai, w1);
                }
            }
        }
        __syncthreads();

        float q00 = pb1s[2*tx], q01 = pb1s[2*tx+1];
        float q10 = pb1s[2*tx+32], q11 = pb1s[2*tx+33];
        #pragma unroll
        for (int i = 0; i < 8; i++) {
            float2 p0 = unpk(acc[i][0]), p1 = unpk(acc[i][1]);
            float* rowp = s1S + (ty*8 + i)*68;
            *((float2*)(rowp + 2*tx))      = make_float2(p0.x + q00, p0.y + q01);
            *((float2*)(rowp + 2*tx + 32)) = make_float2(p1.x + q10, p1.y + q11);
        }
    }
    __syncthreads();

    if (t < 64) {
        int node = nb + t;
        if (node < NN) {
            float v[64];
            #pragma unroll
            for (int c4 = 0; c4 < 16; c4++)
                ((float4*)v)[c4] = ((const float4*)(s1S + t*68))[c4];
            float mu = 0.f, msq = 0.f;
            #pragma unroll
            for (int c = 0; c < 64; c++) { mu += v[c]; msq += v[c]*v[c]; }
            mu *= (1.f/64.f); msq *= (1.f/64.f);
            float rstd = rsqrtf(msq - mu*mu + LN_EPS);
            float mx = -1e30f;
            #pragma unroll
            for (int c = 0; c < 64; c++) {
                v[c] = (v[c] - mu) * rstd * g1s[c] + be1s[c];
                mx = fmaxf(mx, v[c]);
            }
            float es = 0.f;
            #pragma unroll
            for (int c = 0; c < 64; c++) es += __expf(v[c] - mx);
            float lse = mx + __logf(es);
            float* lsp = ls1out + (size_t)node*C1N;
            float* sp  = d_s + (size_t)node*C1N;
            #pragma unroll
            for (int c4 = 0; c4 < 16; c4++) {
                float l0 = v[c4*4+0]-lse, l1 = v[c4*4+1]-lse, l2 = v[c4*4+2]-lse, l3 = v[c4*4+3]-lse;
                ((float4*)lsp)[c4] = make_float4(l0, l1, l2, l3);
                ((float4*)sp)[c4]  = make_float4(__expf(l0), __expf(l1), __expf(l2), __expf(l3));
            }
        }
    }
}

// ---------------- kmerge1: scatter2 (blocks 0..4095) + k5x (4096..4391) ----------------
// k5x: pooled_x (cols 0..127) + sTs (cols 192..255) from d_x1/d_s
__global__ void __launch_bounds__(256, 3) kmerge1(const int* __restrict__ row,
                                                  const int* __restrict__ col) {
    if (blockIdx.x < 4096) {
        int i0 = blockIdx.x*256 + threadIdx.x, st = 4096*256;
        for (int i = i0; i < EE*16; i += st) {
            int e = i >> 4, c = i & 15;
            int srcn = col[e];
            int dstn = row[e];
            float4 v = ((const float4*)(d_s + (size_t)srcn*C1N))[c];
            red_add4((float*)(((float4*)(d_As + (size_t)dstn*C1N)) + c), v);
        }
        return;
    }
    // ---- k5x ----
    __shared__ __align__(16) float V8[8][192];
    int bx = blockIdx.x - 4096;   // 0..295
    int t = threadIdx.x;

    u64 acc[32];
    #pragma unroll
    for (int p = 0; p < 32; p++) acc[p] = 0;

    int per = (NN + 295) / 296;
    int n0 = bx * per;
    int n1 = n0 + per; if (n1 > NN) n1 = NN;

    for (int nb = n0; nb < n1; nb += 8) {
        int cnt = n1 - nb; if (cnt > 8) cnt = 8;
        for (int i = t; i < cnt*192; i += 256) {
            int ni = i / 192, c = i % 192;
            size_t node = (size_t)(nb + ni);
            V8[ni][c] = (c < 128) ? d_x1[node*HC + c] : d_s[node*C1N + (c - 128)];
        }
        __syncthreads();
        if (t < 192) {
            for (int ni = 0; ni < cnt; ni++) {
                u64 vd = dup2(V8[ni][t]);
                const u64* sp = (const u64*)(&V8[ni][128]);
                #pragma unroll
                for (int p = 0; p < 32; p++) ffma2(acc[p], sp[p], vd);
            }
        }
        __syncthreads();
    }

    if (t < 192) {
        int colout = (t < 128) ? t : (t + 64);   // s-cols -> 192..255
        #pragma unroll
        for (int p = 0; p < 32; p++) {
            float2 pr = unpk(acc[p]);
            atomicAdd(&d_pooled[(2*p+0)*256 + colout], pr.x);
            atomicAdd(&d_pooled[(2*p+1)*256 + colout], pr.y);
        }
    }
}

// ---------------- k5a: pooled_adj (cols 128..191) + den, from d_As/d_s ----------------
__global__ void __launch_bounds__(256, 3) k5a() {
    __shared__ __align__(16) float V[8][128];   // c<64: As, c<128: s
    __shared__ float D8p[8][8];
    __shared__ float D8[8];
    __shared__ float redw[8];

    int t = threadIdx.x;
    u64 acc[32];
    #pragma unroll
    for (int p = 0; p < 32; p++) acc[p] = 0;
    float denAcc = 0.f;

    int per = (NN + gridDim.x - 1) / gridDim.x;
    int n0 = blockIdx.x * per;
    int n1 = n0 + per; if (n1 > NN) n1 = NN;

    for (int nb = n0; nb < n1; nb += 8) {
        int cnt = n1 - nb; if (cnt > 8) cnt = 8;
        for (int i = t; i < cnt*128; i += 256) {
            int ni = i >> 7, c = i & 127;
            size_t node = (size_t)(nb + ni);
            V[ni][c] = (c < 64) ? d_As[node*C1N + c] : d_s[node*C1N + (c - 64)];
        }
        __syncthreads();

        // deg from As rowsums
        for (int i = t; i < cnt*8; i += 256) {
            int ni = i >> 3, seg = i & 7;
            const float* vp = &V[ni][seg*8];
            float sacc = 0.f;
            #pragma unroll
            for (int j = 0; j < 8; j++) sacc += vp[j];
            D8p[ni][seg] = sacc;
        }
        __syncthreads();
        if (t < cnt) {
            float s = 0.f;
            #pragma unroll
            for (int j = 0; j < 8; j++) s += D8p[t][j];
            D8[t] = s;
        }

        if (t < 64) {
            for (int ni = 0; ni < cnt; ni++) {
                u64 vd = dup2(V[ni][t]);
                const u64* sp = (const u64*)(&V[ni][64]);
                #pragma unroll
                for (int p = 0; p < 32; p++) ffma2(acc[p], sp[p], vd);
            }
        }
        __syncthreads();
        for (int i = t; i < cnt*64; i += 256) {
            int ni = i >> 6, a = i & 63;
            float sv = V[ni][64 + a];
            denAcc += D8[ni] * sv * sv;
        }
        __syncthreads();
    }

    if (t < 64) {
        #pragma unroll
        for (int p = 0; p < 32; p++) {
            float2 pr = unpk(acc[p]);
            atomicAdd(&d_pooled[(2*p+0)*256 + 128 + t], pr.x);
            atomicAdd(&d_pooled[(2*p+1)*256 + 128 + t], pr.y);
        }
    }

    #pragma unroll
    for (int o = 16; o; o >>= 1) denAcc += __shfl_xor_sync(0xffffffffu, denAcc, o);
    if ((t & 31) == 0) redw[t >> 5] = denAcc;
    __syncthreads();
    if (t == 0) {
        float s = 0.f;
        for (int w = 0; w < 8; w++) s += redw[w];
        atomicAdd(&d_den, s);
    }
}

// ---------------- k6 (unchanged from R15) ----------------
__device__ __forceinline__ float k6_sum(float v, float* redw, float* scal) {
    #pragma unroll
    for (int o = 16; o; o >>= 1) v += __shfl_xor_sync(0xffffffffu, v, o);
    if ((threadIdx.x & 31) == 0) redw[threadIdx.x >> 5] = v;
    __syncthreads();
    if (threadIdx.x == 0) {
        float s = 0.f;
        for (int w = 0; w < 8; w++) s += redw[w];
        scal[0] = s;
    }
    __syncthreads();
    float r = scal[0];
    __syncthreads();
    return r;
}

#define O_PX    0
#define O_MS    8448
#define O_T1    12544
#define O_X2    20992
#define O_PA    29184
#define O_STS   33280
#define O_PW2   37376
#define O_S2R   39424
#define O_S2    40448
#define O_AS2   41472
#define O_PA2   42496
#define O_STS2  42752
#define O_DSI   43008
#define O_DEG2  43072
#define O_REDW  43136
#define O_SCAL  43200
#define O_WS    43208
#define K6_SMEM_FLOATS (43208 + 2*2048)
#define K6_SMEM_BYTES (K6_SMEM_FLOATS*4)

__global__ void __launch_bounds__(256, 1) k6(
    const float* __restrict__ b2,
    const float* __restrict__ pb2,
    const float* __restrict__ g2, const float* __restrict__ be2,
    float* __restrict__ out, float* __restrict__ ls2out) {
    extern __shared__ float sm[];
    float* px    = sm + O_PX;
    float* Ms    = sm + O_MS;
    float* t1S   = sm + O_T1;
    float* x2S   = sm + O_X2;
    float* paS   = sm + O_PA;
    float* stsS  = sm + O_STS;
    float* pW2S  = sm + O_PW2;
    float* s2raw = sm + O_S2R;
    float* s2S   = sm + O_S2;
    float* As2   = sm + O_AS2;
    float* pa2   = sm + O_PA2;
    float* sts2  = sm + O_STS2;
    float* dsi   = sm + O_DSI;
    float* deg2  = sm + O_DEG2;
    float* redw  = sm + O_REDW;
    float* scal  = sm + O_SCAL;
    float* WS    = sm + O_WS;

    int t = threadIdx.x;
    u32 ws_u32 = smem_u32(WS);

    #pragma unroll
    for (int p = 0; p < 2; p++) {
        int f4 = t + 256*p;
        cp16(ws_u32 + f4*16, d_W2relT + f4*4);
    }
    asm volatile("cp.async.commit_group;" ::: "memory");

    for (int i = t; i < 8192; i += 256) px[(i >> 7)*132 + (i & 127)] = d_pooled[((i >> 7) << 8) + (i & 127)];
    for (int i = t; i < 4096; i += 256) paS[i]  = d_pooled[((i >> 6) << 8) + 128 + (i & 63)];
    for (int i = t; i < 4096; i += 256) stsS[i] = d_pooled[((i >> 6) << 8) + 192 + (i & 63)];
    for (int i = t; i < 2048; i += 256) pW2S[i] = d_pW2t[i];
    __syncthreads();

    float tr = k6_sum((t < 64) ? paS[t*64 + t] : 0.f, redw, scal);
    float mc1 = -tr / (d_den + 1e-10f);

    float fq = 0.f;
    for (int i = t; i < 4096; i += 256) { float u = stsS[i]; fq += u*u; }
    float norm = sqrtf(k6_sum(fq, redw, scal));
    float oq = 0.f;
    for (int i = t; i < 4096; i += 256) {
        float u = stsS[i] / (norm + 1e-10f) - (((i >> 6) == (i & 63)) ? 0.125f : 0.f);
        oq += u*u;
    }
    float o1 = sqrtf(k6_sum(oq, redw, scal));

    if (t < 64) {
        float rs = 0.f;
        for (int b = 0; b < 64; b++) if (b != t) rs += paS[t*64 + b];
        dsi[t] = 1.f / (sqrtf(rs) + 1e-15f);
    }
    __syncthreads();
    for (int i = t; i < 4096; i += 256) {
        int a = i >> 6, b = i & 63;
        float adjn = (a == b) ? 0.f : paS[i] * dsi[a] * dsi[b];
        Ms[i] = (adjn > THRESH1) ? 1.f : 0.f;
    }
    __syncthreads();

    for (int i = t; i < 2048; i += 256) {
        int a = i >> 5, f4 = i & 31;
        float4 acc = make_float4(0.f, 0.f, 0.f, 0.f);
        for (int b = 0; b < 64; b++) {
            float ms = Ms[b*64 + a];
            float4 pv = ((const float4*)(px + b*132))[f4];
            acc.x += ms*pv.x; acc.y += ms*pv.y; acc.z += ms*pv.z; acc.w += ms*pv.w;
        }
        ((float4*)(t1S + a*132))[f4] = acc;
    }

    int tx = t & 15, ty = t >> 4;
    u64 acc2[4][4];
    #pragma unroll
    for (int j = 0; j < 4; j++) { acc2[j][0]=0; acc2[j][1]=0; acc2[j][2]=0; acc2[j][3]=0; }

    for (int c = 0; c < 16; c++) {
        asm volatile("cp.async.wait_group 0;" ::: "memory");
        __syncthreads();
        if (c < 15) {
            const float* src = (c + 1 < 8) ? (d_W2relT + (c+1)*2048) : (d_W2rootT + (c+1-8)*2048);
            u32 dst = ws_u32 + ((c+1) & 1)*2048*4;
            #pragma unroll
            for (int p = 0; p < 2; p++) {
                int f4 = t + 256*p;
                cp16(dst + f4*16, src + f4*4);
            }
            asm volatile("cp.async.commit_group;" ::: "memory");
        }
        const float* Wb = WS + (c & 1)*2048;
        const float* Asrc = (c < 8) ? t1S : px;
        int fbase = (c & 7)*16;
        #pragma unroll
        for (int kk = 0; kk < 16; kk++) {
            int f = fbase + kk;
            const u64* wr = (const u64*)(Wb + kk*128 + tx*8);
            u64 w0 = wr[0], w1 = wr[1], w2 = wr[2], w3 = wr[3];
            #pragma unroll
            for (int j = 0; j < 4; j++) {
                u64 Aj = dup2(Asrc[(ty*4 + j)*132 + f]);
                ffma2(acc2[j][0], Aj, w0); ffma2(acc2[j][1], Aj, w1);
                ffma2(acc2[j][2], Aj, w2); ffma2(acc2[j][3], Aj, w3);
            }
        }
    }
    {
        float bb[8];
        #pragma unroll
        for (int p = 0; p < 8; p++) bb[p] = b2[tx*8 + p];
        #pragma unroll
        for (int j = 0; j < 4; j++) {
            int a = ty*4 + j;
            float2 p0 = unpk(acc2[j][0]), p1 = unpk(acc2[j][1]);
            float2 p2 = unpk(acc2[j][2]), p3 = unpk(acc2[j][3]);
            float4 o0 = make_float4(fmaxf(p0.x+bb[0],0.f), fmaxf(p0.y+bb[1],0.f),
                                    fmaxf(p1.x+bb[2],0.f), fmaxf(p1.y+bb[3],0.f));
            float4 o1 = make_float4(fmaxf(p2.x+bb[4],0.f), fmaxf(p2.y+bb[5],0.f),
                                    fmaxf(p3.x+bb[6],0.f), fmaxf(p3.y+bb[7],0.f));
            ((float4*)(x2S + a*128 + tx*8))[0] = o0;
            ((float4*)(x2S + a*128 + tx*8))[1] = o1;
        }
    }
    __syncthreads();

    for (int i = t; i < 1024; i += 256) {
        int a = i >> 4, c = i & 15;
        float acc = pb2[c];
        for (int h = 0; h < 128; h++) acc += x2S[a*128 + h] * pW2S[h*16 + c];
        s2raw[i] = acc;
    }
    __syncthreads();

    if (t < 64) {
        float mu = 0.f, msq = 0.f;
        for (int c = 0; c < 16; c++) { float u = s2raw[t*16 + c]; mu += u; msq += u*u; }
        mu *= (1.f/16.f); msq *= (1.f/16.f);
        float rstd = rsqrtf(msq - mu*mu + LN_EPS);
        float nv[16]; float mx = -1e30f;
        for (int c = 0; c < 16; c++) {
            nv[c] = (s2raw[t*16 + c] - mu) * rstd * g2[c] + be2[c];
            mx = fmaxf(mx, nv[c]);
        }
        float es = 0.f;
        for (int c = 0; c < 16; c++) es += expf(nv[c] - mx);
        float lse = mx + logf(es);
        for (int c = 0; c < 16; c++) {
            float ls = nv[c] - lse;
            ls2out[t*16 + c] = ls;
            s2S[t*16 + c] = expf(ls);
        }
        float dg = 0.f;
        for (int b = 0; b < 64; b++) dg += Ms[t*64 + b];
        deg2[t] = dg;
    }
    __syncthreads();

    for (int i = t; i < 1024; i += 256) {
        int a = i >> 4, c = i & 15;
        float acc = 0.f;
        for (int b = 0; b < 64; b++) acc += Ms[a*64 + b] * s2S[b*16 + c];
        As2[i] = acc;
    }
    __syncthreads();

    {
        int p = t >> 4, q = t & 15;
        float a1 = 0.f, a2 = 0.f;
        for (int a = 0; a < 64; a++) {
            float sp = s2S[a*16 + p];
            a1 += sp * As2[a*16 + q];
            a2 += sp * s2S[a*16 + q];
        }
        pa2[t] = a1; sts2[t] = a2;
    }
    __syncthreads();

    float tr2 = k6_sum((t < 16) ? pa2[t*17] : 0.f, redw, scal);
    float dv = 0.f;
    if (t < 64) {
        float q2 = 0.f;
        for (int c = 0; c < 16; c++) { float u = s2S[t*16 + c]; q2 += u*u; }
        dv = deg2[t] * q2;
    }
    float den2 = k6_sum(dv, redw, scal) + 1e-10f;
    float mc2 = -tr2 / den2;

    float f2 = sts2[t] * sts2[t];
    float norm2 = sqrtf(k6_sum(f2, redw, scal));
    float u2 = sts2[t] / (norm2 + 1e-10f) - (((t >> 4) == (t & 15)) ? 0.25f : 0.f);
    float o2 = sqrtf(k6_sum(u2*u2, redw, scal));

    if (t == 0) { out[0] = mc1; out[1] = o1; out[2] = mc2; out[3] = o2; }
}

// ---------------- launch ----------------
extern "C" void kernel_launch(void* const* d_in, const int* in_sizes, int n_in,
                              void* d_out, int out_size) {
    const float* x      = (const float*)d_in[0];
    const int*   ei     = (const int*)  d_in[1];
    const float* dm     = (const float*)d_in[2];
    const float* W1rel  = (const float*)d_in[3];
    const float* b1     = (const float*)d_in[4];
    const float* W1root = (const float*)d_in[5];
    const float* pW1    = (const float*)d_in[6];
    const float* pb1    = (const float*)d_in[7];
    const float* g1     = (const float*)d_in[8];
    const float* be1    = (const float*)d_in[9];
    const float* W2rel  = (const float*)d_in[10];
    const float* b2     = (const float*)d_in[11];
    const float* W2root = (const float*)d_in[12];
    const float* pW2    = (const float*)d_in[13];
    const float* pb2    = (const float*)d_in[14];
    const float* g2     = (const float*)d_in[15];
    const float* be2    = (const float*)d_in[16];
    float* out = (float*)d_out;
    const int* row = ei;
    const int* col = ei + EE;

    cudaFuncSetAttribute(kAB, cudaFuncAttributeMaxDynamicSharedMemorySize, KAB_SMEM_BYTES);
    cudaFuncSetAttribute(k6, cudaFuncAttributeMaxDynamicSharedMemorySize, K6_SMEM_BYTES);

    int nblk = (NN + 63) / 64;  // 782

    kinitA<<<512, 256>>>();
    kmerge0<<<4352, 256>>>(x, dm, row, col, W1rel, W1root, pW1, W2rel, W2root, pW2);
    kAB<<<nblk, 128, KAB_SMEM_BYTES>>>(x, dm, b1, pb1, g1, be1, out + 4);
    kmerge1<<<4392, 256>>>(row, col);
    k5a<<<296, 256>>>();
    k6<<<1, 256, K6_SMEM_BYTES>>>(b2, pb2, g2, be2, out, out + 4 + (size_t)NN*C1N);
}

// round 17
// speedup vs baseline: 1.3421x; 1.3421x over previous
#include <cuda_runtime.h>
#include <math.h>

#define NN 50000
#define EE 800000
#define INC 64
#define HC 128
#define C1N 64
#define C2N 16
#define LN_EPS 1e-5f
#define THRESH1 (1.0f/63.0f)

typedef unsigned long long u64;
typedef unsigned int u32;

// ---------------- device scratch ----------------
__device__ __align__(16) float d_agg[NN*INC];
__device__ __align__(16) float d_x1[NN*HC];
__device__ __align__(16) float d_s[NN*C1N];
__device__ __align__(16) float d_As[NN*C1N];
__device__ __align__(16) float d_pooled[C1N*256];
__device__ float d_den;
__device__ __align__(16) float d_Wcat[HC*HC];    // [k][h]
__device__ __align__(16) float d_pW1t[HC*C1N];   // [k][c]
__device__ __align__(16) float d_W2relT[HC*HC];  // [f][h]
__device__ __align__(16) float d_W2rootT[HC*HC]; // [f][h]
__device__ __align__(16) float d_pW2t[HC*C2N];   // [h][c]

__device__ __forceinline__ void red_add4(float* addr, float4 v) {
    asm volatile("red.global.add.v4.f32 [%0], {%1,%2,%3,%4};"
                 :: "l"(addr), "f"(v.x), "f"(v.y), "f"(v.z), "f"(v.w) : "memory");
}
__device__ __forceinline__ u64 dup2(float a) {
    u64 r; asm("mov.b64 %0, {%1, %1};" : "=l"(r) : "f"(a)); return r;
}
__device__ __forceinline__ void ffma2(u64& d, u64 a, u64 b) {
    asm("fma.rn.f32x2 %0, %1, %2, %0;" : "+l"(d) : "l"(a), "l"(b));
}
__device__ __forceinline__ float2 unpk(u64 v) {
    float2 r; asm("mov.b64 {%0, %1}, %2;" : "=f"(r.x), "=f"(r.y) : "l"(v)); return r;
}
__device__ __forceinline__ u64 ldg64(const float* p) {
    return __ldg((const unsigned long long*)p);
}
__device__ __forceinline__ u32 smem_u32(const void* p) {
    u32 a;
    asm("{ .reg .u64 tmp; cvta.to.shared.u64 tmp, %1; cvt.u32.u64 %0, tmp; }" : "=r"(a) : "l"(p));
    return a;
}
__device__ __forceinline__ void cp16(u32 dst, const void* src) {
    asm volatile("cp.async.cg.shared.global [%0], [%1], 16;" :: "r"(dst), "l"(src));
}

// ---------------- kinitA: zero d_agg only (gates scatter1) ----------------
__global__ void kinitA() {
    int i0 = blockIdx.x*blockDim.x + threadIdx.x, st = gridDim.x*blockDim.x;
    float4 z = make_float4(0.f,0.f,0.f,0.f);
    for (int i = i0; i < NN*INC/4; i += st) ((float4*)d_agg)[i] = z;
}

// ---------------- kmerge0: scatter1 (blocks 0..4095) + initB (4096..4351) ----------------
// both roles are register-light (~28 regs) -> no occupancy coupling
__global__ void kmerge0(const float* __restrict__ x, const float* __restrict__ dm,
                        const int* __restrict__ row, const int* __restrict__ col,
                        const float* __restrict__ W1rel, const float* __restrict__ W1root,
                        const float* __restrict__ pW1,
                        const float* __restrict__ W2rel, const float* __restrict__ W2root,
                        const float* __restrict__ pW2) {
    if (blockIdx.x < 4096) {
        int i0 = blockIdx.x*256 + threadIdx.x, st = 4096*256;
        for (int i = i0; i < EE*16; i += st) {
            int e = i >> 4, c = i & 15;
            int r = row[e];
            float m = dm[r];
            if (m != 0.0f) {
                int d = col[e];
                float4 v = ((const float4*)(x + (size_t)r*INC))[c];
                v.x *= m; v.y *= m; v.z *= m; v.w *= m;
                red_add4((float*)(((float4*)(d_agg + (size_t)d*INC)) + c), v);
            }
        }
    } else {
        int j0 = (blockIdx.x - 4096)*256 + threadIdx.x, st = 256*256;
        float4 z = make_float4(0.f,0.f,0.f,0.f);
        for (int i = j0; i < NN*INC/4; i += st) ((float4*)d_As)[i] = z;
        for (int i = j0; i < C1N*64;   i += st) ((float4*)d_pooled)[i] = z;
        if (j0 == 0) d_den = 0.f;
        for (int i = j0; i < HC*HC; i += st) {
            int k = i >> 7, h = i & 127;
            d_Wcat[i] = (k < 64) ? W1rel[h*64 + k] : W1root[h*64 + (k - 64)];
            d_W2relT[i]  = W2rel[h*128 + k];
            d_W2rootT[i] = W2root[h*128 + k];
        }
        for (int i = j0; i < HC*C1N; i += st) {
            int k = i >> 6, c = i & 63;
            d_pW1t[i] = pW1[c*128 + k];
        }
        for (int i = j0; i < HC*C2N; i += st) {
            int h = i >> 4, c = i & 15;
            d_pW2t[i] = pW2[c*128 + h];
        }
    }
}

// ---------------- kAB: fused X1 + s1 pipeline ----------------
#define KAB_OVL_FLOATS (64*68)
#define KAB_SMEM_FLOATS (128*68 + KAB_OVL_FLOATS + 192)
#define KAB_SMEM_BYTES  (KAB_SMEM_FLOATS*4)

__global__ void __launch_bounds__(128, 4) kAB(const float* __restrict__ x,
                                              const float* __restrict__ dm,
                                              const float* __restrict__ b1,
                                              const float* __restrict__ pb1,
                                              const float* __restrict__ g1,
                                              const float* __restrict__ be1,
                                              float* __restrict__ ls1out) {
    extern __shared__ float sm[];
    float* As   = sm;
    float* ovl  = As + 128*68;
    float* pb1s = ovl + KAB_OVL_FLOATS;
    float* g1s  = pb1s + 64;
    float* be1s = g1s + 64;
    float* s1S  = ovl;

    int t = threadIdx.x;
    u32 ovl_u32 = smem_u32(ovl);

    #pragma unroll
    for (int p = 0; p < 4; p++) {
        int f4 = t + 128*p;
        cp16(ovl_u32 + f4*16, d_Wcat + f4*4);
    }
    asm volatile("cp.async.commit_group;" ::: "memory");

    if (t < 64) { pb1s[t] = pb1[t]; g1s[t] = g1[t]; be1s[t] = be1[t]; }

    int nb = blockIdx.x * 64;
    {
        int m = t & 63, grp = t >> 6;
        int node = nb + m;
        bool valid = node < NN;
        float dmn = valid ? dm[node] : 0.f;
        for (int q = grp; q < 32; q += 2) {
            float4 v;
            if (valid) {
                if (q < 16) v = ((const float4*)(d_agg + (size_t)node*INC))[q];
                else {
                    v = ((const float4*)(x + (size_t)node*INC))[q - 16];
                    v.x *= dmn; v.y *= dmn; v.z *= dmn; v.w *= dmn;
                }
            } else v = make_float4(0.f, 0.f, 0.f, 0.f);
            int k0 = q * 4;
            As[(k0+0)*68 + m] = v.x;
            As[(k0+1)*68 + m] = v.y;
            As[(k0+2)*68 + m] = v.z;
            As[(k0+3)*68 + m] = v.w;
        }
    }

    int tx = t & 15, ty = t >> 4;
    {
        u64 acc[8][4];
        #pragma unroll
        for (int i = 0; i < 8; i++) { acc[i][0]=0; acc[i][1]=0; acc[i][2]=0; acc[i][3]=0; }

        for (int c = 0; c < 8; c++) {
            asm volatile("cp.async.wait_group 0;" ::: "memory");
            __syncthreads();
            if (c < 7) {
                const float* src = d_Wcat + (c+1)*2048;
                u32 dst = ovl_u32 + ((c+1) & 1)*2048*4;
                #pragma unroll
                for (int p = 0; p < 4; p++) {
                    int f4 = t + 128*p;
                    cp16(dst + f4*16, src + f4*4);
                }
                asm volatile("cp.async.commit_group;" ::: "memory");
            }
            const float* Wb = ovl + (c & 1)*2048;
            #pragma unroll
            for (int kk = 0; kk < 16; kk++) {
                int k = c*16 + kk;
                const float* ap = As + k*68 + ty*8;
                float4 aA = *(const float4*)ap;
                float4 aB = *(const float4*)(ap + 4);
                const u64* wr = (const u64*)(Wb + kk*128);
                u64 w0 = wr[tx], w1 = wr[tx+16], w2 = wr[tx+32], w3 = wr[tx+48];
                float av[8] = {aA.x, aA.y, aA.z, aA.w, aB.x, aB.y, aB.z, aB.w};
                #pragma unroll
                for (int i = 0; i < 8; i++) {
                    u64 Ai = dup2(av[i]);
                    ffma2(acc[i][0], Ai, w0);
                    ffma2(acc[i][1], Ai, w1);
                    ffma2(acc[i][2], Ai, w2);
                    ffma2(acc[i][3], Ai, w3);
                }
            }
        }
        __syncthreads();

        float bb[8];
        #pragma unroll
        for (int j = 0; j < 4; j++) { bb[2*j] = b1[2*tx + 32*j]; bb[2*j+1] = b1[2*tx + 1 + 32*j]; }
        #pragma unroll
        for (int i = 0; i < 8; i++) {
            int m = ty*8 + i;
            int nd = nb + m;
            #pragma unroll
            for (int j = 0; j < 4; j++) {
                float2 p = unpk(acc[i][j]);
                float2 o = make_float2(fmaxf(p.x + bb[2*j], 0.f), fmaxf(p.y + bb[2*j+1], 0.f));
                int h = 2*tx + 32*j;
                As[h*68 + m]     = o.x;
                As[(h+1)*68 + m] = o.y;
                if (nd < NN) *((float2*)(d_x1 + (size_t)nd*HC + h)) = o;
            }
        }
    }
    {
        #pragma unroll
        for (int p = 0; p < 2; p++) {
            int f4 = t + 128*p;
            cp16(ovl_u32 + f4*16, d_pW1t + f4*4);
        }
        asm volatile("cp.async.commit_group;" ::: "memory");
    }

    {
        u64 acc[8][2];
        #pragma unroll
        for (int i = 0; i < 8; i++) { acc[i][0]=0; acc[i][1]=0; }

        for (int c = 0; c < 8; c++) {
            asm volatile("cp.async.wait_group 0;" ::: "memory");
            __syncthreads();
            if (c < 7) {
                const float* src = d_pW1t + (c+1)*1024;
                u32 dst = ovl_u32 + ((c+1) & 1)*1024*4;
                #pragma unroll
                for (int p = 0; p < 2; p++) {
                    int f4 = t + 128*p;
                    cp16(dst + f4*16, src + f4*4);
                }
                asm volatile("cp.async.commit_group;" ::: "memory");
            }
            const float* Wb = ovl + (c & 1)*1024;
            #pragma unroll
            for (int kk = 0; kk < 16; kk++) {
                int k = c*16 + kk;
                const float* ap = As + k*68 + ty*8;
                float4 aA = *(const float4*)ap;
                float4 aB = *(const float4*)(ap + 4);
                const u64* wr = (const u64*)(Wb + kk*64);
                u64 w0 = wr[tx], w1 = wr[tx+16];
                float av[8] = {aA.x, aA.y, aA.z, aA.w, aB.x, aB.y, aB.z, aB.w};
                #pragma unroll
                for (int i = 0; i < 8; i++) {
                    u64 Ai = dup2(av[i]);
                    ffma2(acc[i][0], Ai, w0);
                    ffma2(acc[i][1], Ai, w1);
                }
            }
        }
        __syncthreads();

        float q00 = pb1s[2*tx], q01 = pb1s[2*tx+1];
        float q10 = pb1s[2*tx+32], q11 = pb1s[2*tx+33];
        #pragma unroll
        for (int i = 0; i < 8; i++) {
            float2 p0 = unpk(acc[i][0]), p1 = unpk(acc[i][1]);
            float* rowp = s1S + (ty*8 + i)*68;
            *((float2*)(rowp + 2*tx))      = make_float2(p0.x + q00, p0.y + q01);
            *((float2*)(rowp + 2*tx + 32)) = make_float2(p1.x + q10, p1.y + q11);
        }
    }
    __syncthreads();

    if (t < 64) {
        int node = nb + t;
        if (node < NN) {
            float v[64];
            #pragma unroll
            for (int c4 = 0; c4 < 16; c4++)
                ((float4*)v)[c4] = ((const float4*)(s1S + t*68))[c4];
            float mu = 0.f, msq = 0.f;
            #pragma unroll
            for (int c = 0; c < 64; c++) { mu += v[c]; msq += v[c]*v[c]; }
            mu *= (1.f/64.f); msq *= (1.f/64.f);
            float rstd = rsqrtf(msq - mu*mu + LN_EPS);
            float mx = -1e30f;
            #pragma unroll
            for (int c = 0; c < 64; c++) {
                v[c] = (v[c] - mu) * rstd * g1s[c] + be1s[c];
                mx = fmaxf(mx, v[c]);
            }
            float es = 0.f;
            #pragma unroll
            for (int c = 0; c < 64; c++) es += __expf(v[c] - mx);
            float lse = mx + __logf(es);
            float* lsp = ls1out + (size_t)node*C1N;
            float* sp  = d_s + (size_t)node*C1N;
            #pragma unroll
            for (int c4 = 0; c4 < 16; c4++) {
                float l0 = v[c4*4+0]-lse, l1 = v[c4*4+1]-lse, l2 = v[c4*4+2]-lse, l3 = v[c4*4+3]-lse;
                ((float4*)lsp)[c4] = make_float4(l0, l1, l2, l3);
                ((float4*)sp)[c4]  = make_float4(__expf(l0), __expf(l1), __expf(l2), __expf(l3));
            }
        }
    }
}

// ---------------- scatter 2 (standalone, occupancy-preserved) ----------------
__global__ void kscatter2(const int* __restrict__ row, const int* __restrict__ col) {
    int i0 = blockIdx.x*blockDim.x + threadIdx.x, st = gridDim.x*blockDim.x;
    for (int i = i0; i < EE*16; i += st) {
        int e = i >> 4, c = i & 15;
        int srcn = col[e];
        int dstn = row[e];
        float4 v = ((const float4*)(d_s + (size_t)srcn*C1N))[c];
        red_add4((float*)(((float4*)(d_As + (size_t)dstn*C1N)) + c), v);
    }
}

// ---------------- k5 (R15 version): pooled reduction; s read once via V8 ----------------
__global__ void __launch_bounds__(256, 2) k5() {
    __shared__ __align__(16) float V8[8][256];
    __shared__ float D8p[8][8];
    __shared__ float D8[8];
    __shared__ float redw[8];

    u64 acc[32];
    #pragma unroll
    for (int p = 0; p < 32; p++) acc[p] = 0;
    float denAcc = 0.f;

    int t = threadIdx.x;
    int per = (NN + gridDim.x - 1) / gridDim.x;
    int n0 = blockIdx.x * per;
    int n1 = n0 + per; if (n1 > NN) n1 = NN;

    for (int nb = n0; nb < n1; nb += 8) {
        int cnt = n1 - nb; if (cnt > 8) cnt = 8;
        for (int i = t; i < cnt*256; i += 256) {
            int ni = i >> 8, c = i & 255;
            size_t node = (size_t)(nb + ni);
            float val;
            if (c < 128)      val = d_x1[node*HC + c];
            else if (c < 192) val = d_As[node*C1N + (c - 128)];
            else              val = d_s[node*C1N + (c - 192)];
            V8[ni][c] = val;
        }
        __syncthreads();

        for (int i = t; i < cnt*8; i += 256) {
            int ni = i >> 3, seg = i & 7;
            const float* vp = &V8[ni][128 + seg*8];
            float sacc = 0.f;
            #pragma unroll
            for (int j = 0; j < 8; j++) sacc += vp[j];
            D8p[ni][seg] = sacc;
        }
        __syncthreads();
        if (t < cnt) {
            float s = 0.f;
            #pragma unroll
            for (int j = 0; j < 8; j++) s += D8p[t][j];
            D8[t] = s;
        }

        for (int ni = 0; ni < cnt; ni++) {
            u64 vd = dup2(V8[ni][t]);
            const u64* sp = (const u64*)(&V8[ni][192]);
            #pragma unroll
            for (int p = 0; p < 32; p++) ffma2(acc[p], sp[p], vd);
        }
        __syncthreads();
        for (int i = t; i < cnt*64; i += 256) {
            int ni = i >> 6, a = i & 63;
            float sv = V8[ni][192 + a];
            denAcc += D8[ni] * sv * sv;
        }
        __syncthreads();
    }

    #pragma unroll
    for (int p = 0; p < 32; p++) {
        float2 pr = unpk(acc[p]);
        atomicAdd(&d_pooled[(2*p+0)*256 + t], pr.x);
        atomicAdd(&d_pooled[(2*p+1)*256 + t], pr.y);
    }

    #pragma unroll
    for (int o = 16; o; o >>= 1) denAcc += __shfl_xor_sync(0xffffffffu, denAcc, o);
    if ((t & 31) == 0) redw[t >> 5] = denAcc;
    __syncthreads();
    if (t == 0) {
        float s = 0.f;
        for (int w = 0; w < 8; w++) s += redw[w];
        atomicAdd(&d_den, s);
    }
}

// ---------------- k6 ----------------
__device__ __forceinline__ float k6_sum(float v, float* redw, float* scal) {
    #pragma unroll
    for (int o = 16; o; o >>= 1) v += __shfl_xor_sync(0xffffffffu, v, o);
    if ((threadIdx.x & 31) == 0) redw[threadIdx.x >> 5] = v;
    __syncthreads();
    if (threadIdx.x == 0) {
        float s = 0.f;
        for (int w = 0; w < 8; w++) s += redw[w];
        scal[0] = s;
    }
    __syncthreads();
    float r = scal[0];
    __syncthreads();
    return r;
}

#define O_PX    0
#define O_MS    8448
#define O_T1    12544
#define O_X2    20992
#define O_PA    29184
#define O_STS   33280
#define O_PW2   37376
#define O_S2R   39424
#define O_S2    40448
#define O_AS2   41472
#define O_PA2   42496
#define O_STS2  42752
#define O_DSI   43008
#define O_DEG2  43072
#define O_REDW  43136
#define O_SCAL  43200
#define O_WS    43208
#define K6_SMEM_FLOATS (43208 + 2*2048)
#define K6_SMEM_BYTES (K6_SMEM_FLOATS*4)

__global__ void __launch_bounds__(256, 1) k6(
    const float* __restrict__ b2,
    const float* __restrict__ pb2,
    const float* __restrict__ g2, const float* __restrict__ be2,
    float* __restrict__ out, float* __restrict__ ls2out) {
    extern __shared__ float sm[];
    float* px    = sm + O_PX;
    float* Ms    = sm + O_MS;
    float* t1S   = sm + O_T1;
    float* x2S   = sm + O_X2;
    float* paS   = sm + O_PA;
    float* stsS  = sm + O_STS;
    float* pW2S  = sm + O_PW2;
    float* s2raw = sm + O_S2R;
    float* s2S   = sm + O_S2;
    float* As2   = sm + O_AS2;
    float* pa2   = sm + O_PA2;
    float* sts2  = sm + O_STS2;
    float* dsi   = sm + O_DSI;
    float* deg2  = sm + O_DEG2;
    float* redw  = sm + O_REDW;
    float* scal  = sm + O_SCAL;
    float* WS    = sm + O_WS;

    int t = threadIdx.x;
    u32 ws_u32 = smem_u32(WS);

    #pragma unroll
    for (int p = 0; p < 2; p++) {
        int f4 = t + 256*p;
        cp16(ws_u32 + f4*16, d_W2relT + f4*4);
    }
    asm volatile("cp.async.commit_group;" ::: "memory");

    for (int i = t; i < 8192; i += 256) px[(i >> 7)*132 + (i & 127)] = d_pooled[((i >> 7) << 8) + (i & 127)];
    for (int i = t; i < 4096; i += 256) paS[i]  = d_pooled[((i >> 6) << 8) + 128 + (i & 63)];
    for (int i = t; i < 4096; i += 256) stsS[i] = d_pooled[((i >> 6) << 8) + 192 + (i & 63)];
    for (int i = t; i < 2048; i += 256) pW2S[i] = d_pW2t[i];
    __syncthreads();

    float tr = k6_sum((t < 64) ? paS[t*64 + t] : 0.f, redw, scal);
    float mc1 = -tr / (d_den + 1e-10f);

    float fq = 0.f;
    for (int i = t; i < 4096; i += 256) { float u = stsS[i]; fq += u*u; }
    float norm = sqrtf(k6_sum(fq, redw, scal));
    float oq = 0.f;
    for (int i = t; i < 4096; i += 256) {
        float u = stsS[i] / (norm + 1e-10f) - (((i >> 6) == (i & 63)) ? 0.125f : 0.f);
        oq += u*u;
    }
    float o1 = sqrtf(k6_sum(oq, redw, scal));

    if (t < 64) {
        float rs = 0.f;
        for (int b = 0; b < 64; b++) if (b != t) rs += paS[t*64 + b];
        dsi[t] = 1.f / (sqrtf(rs) + 1e-15f);
    }
    __syncthreads();
    for (int i = t; i < 4096; i += 256) {
        int a = i >> 6, b = i & 63;
        float adjn = (a == b) ? 0.f : paS[i] * dsi[a] * dsi[b];
        Ms[i] = (adjn > THRESH1) ? 1.f : 0.f;
    }
    __syncthreads();

    for (int i = t; i < 2048; i += 256) {
        int a = i >> 5, f4 = i & 31;
        float4 acc = make_float4(0.f, 0.f, 0.f, 0.f);
        for (int b = 0; b < 64; b++) {
            float ms = Ms[b*64 + a];
            float4 pv = ((const float4*)(px + b*132))[f4];
            acc.x += ms*pv.x; acc.y += ms*pv.y; acc.z += ms*pv.z; acc.w += ms*pv.w;
        }
        ((float4*)(t1S + a*132))[f4] = acc;
    }

    int tx = t & 15, ty = t >> 4;
    u64 acc2[4][4];
    #pragma unroll
    for (int j = 0; j < 4; j++) { acc2[j][0]=0; acc2[j][1]=0; acc2[j][2]=0; acc2[j][3]=0; }

    for (int c = 0; c < 16; c++) {
        asm volatile("cp.async.wait_group 0;" ::: "memory");
        __syncthreads();
        if (c < 15) {
            const float* src = (c + 1 < 8) ? (d_W2relT + (c+1)*2048) : (d_W2rootT + (c+1-8)*2048);
            u32 dst = ws_u32 + ((c+1) & 1)*2048*4;
            #pragma unroll
            for (int p = 0; p < 2; p++) {
                int f4 = t + 256*p;
                cp16(dst + f4*16, src + f4*4);
            }
            asm volatile("cp.async.commit_group;" ::: "memory");
        }
        const float* Wb = WS + (c & 1)*2048;
        const float* Asrc = (c < 8) ? t1S : px;
        int fbase = (c & 7)*16;
        #pragma unroll
        for (int kk = 0; kk < 16; kk++) {
            int f = fbase + kk;
            const u64* wr = (const u64*)(Wb + kk*128 + tx*8);
            u64 w0 = wr[0], w1 = wr[1], w2 = wr[2], w3 = wr[3];
            #pragma unroll
            for (int j = 0; j < 4; j++) {
                u64 Aj = dup2(Asrc[(ty*4 + j)*132 + f]);
                ffma2(acc2[j][0], Aj, w0); ffma2(acc2[j][1], Aj, w1);
                ffma2(acc2[j][2], Aj, w2); ffma2(acc2[j][3], Aj, w3);
            }
        }
    }
    {
        float bb[8];
        #pragma unroll
        for (int p = 0; p < 8; p++) bb[p] = b2[tx*8 + p];
        #pragma unroll
        for (int j = 0; j < 4; j++) {
            int a = ty*4 + j;
            float2 p0 = unpk(acc2[j][0]), p1 = unpk(acc2[j][1]);
            float2 p2 = unpk(acc2[j][2]), p3 = unpk(acc2[j][3]);
            float4 o0 = make_float4(fmaxf(p0.x+bb[0],0.f), fmaxf(p0.y+bb[1],0.f),
                                    fmaxf(p1.x+bb[2],0.f), fmaxf(p1.y+bb[3],0.f));
            float4 o1 = make_float4(fmaxf(p2.x+bb[4],0.f), fmaxf(p2.y+bb[5],0.f),
                                    fmaxf(p3.x+bb[6],0.f), fmaxf(p3.y+bb[7],0.f));
            ((float4*)(x2S + a*128 + tx*8))[0] = o0;
            ((float4*)(x2S + a*128 + tx*8))[1] = o1;
        }
    }
    __syncthreads();

    for (int i = t; i < 1024; i += 256) {
        int a = i >> 4, c = i & 15;
        float acc = pb2[c];
        for (int h = 0; h < 128; h++) acc += x2S[a*128 + h] * pW2S[h*16 + c];
        s2raw[i] = acc;
    }
    __syncthreads();

    if (t < 64) {
        float mu = 0.f, msq = 0.f;
        for (int c = 0; c < 16; c++) { float u = s2raw[t*16 + c]; mu += u; msq += u*u; }
        mu *= (1.f/16.f); msq *= (1.f/16.f);
        float rstd = rsqrtf(msq - mu*mu + LN_EPS);
        float nv[16]; float mx = -1e30f;
        for (int c = 0; c < 16; c++) {
            nv[c] = (s2raw[t*16 + c] - mu) * rstd * g2[c] + be2[c];
            mx = fmaxf(mx, nv[c]);
        }
        float es = 0.f;
        for (int c = 0; c < 16; c++) es += expf(nv[c] - mx);
        float lse = mx + logf(es);
        for (int c = 0; c < 16; c++) {
            float ls = nv[c] - lse;
            ls2out[t*16 + c] = ls;
            s2S[t*16 + c] = expf(ls);
        }
        float dg = 0.f;
        for (int b = 0; b < 64; b++) dg += Ms[t*64 + b];
        deg2[t] = dg;
    }
    __syncthreads();

    for (int i = t; i < 1024; i += 256) {
        int a = i >> 4, c = i & 15;
        float acc = 0.f;
        for (int b = 0; b < 64; b++) acc += Ms[a*64 + b] * s2S[b*16 + c];
        As2[i] = acc;
    }
    __syncthreads();

    {
        int p = t >> 4, q = t & 15;
        float a1 = 0.f, a2 = 0.f;
        for (int a = 0; a < 64; a++) {
            float sp = s2S[a*16 + p];
            a1 += sp * As2[a*16 + q];
            a2 += sp * s2S[a*16 + q];
        }
        pa2[t] = a1; sts2[t] = a2;
    }
    __syncthreads();

    float tr2 = k6_sum((t < 16) ? pa2[t*17] : 0.f, redw, scal);
    float dv = 0.f;
    if (t < 64) {
        float q2 = 0.f;
        for (int c = 0; c < 16; c++) { float u = s2S[t*16 + c]; q2 += u*u; }
        dv = deg2[t] * q2;
    }
    float den2 = k6_sum(dv, redw, scal) + 1e-10f;
    float mc2 = -tr2 / den2;

    float f2 = sts2[t] * sts2[t];
    float norm2 = sqrtf(k6_sum(f2, redw, scal));
    float u2 = sts2[t] / (norm2 + 1e-10f) - (((t >> 4) == (t & 15)) ? 0.25f : 0.f);
    float o2 = sqrtf(k6_sum(u2*u2, redw, scal));

    if (t == 0) { out[0] = mc1; out[1] = o1; out[2] = mc2; out[3] = o2; }
}

// ---------------- launch ----------------
extern "C" void kernel_launch(void* const* d_in, const int* in_sizes, int n_in,
                              void* d_out, int out_size) {
    const float* x      = (const float*)d_in[0];
    const int*   ei     = (const int*)  d_in[1];
    const float* dm     = (const float*)d_in[2];
    const float* W1rel  = (const float*)d_in[3];
    const float* b1     = (const float*)d_in[4];
    const float* W1root = (const float*)d_in[5];
    const float* pW1    = (const float*)d_in[6];
    const float* pb1    = (const float*)d_in[7];
    const float* g1     = (const float*)d_in[8];
    const float* be1    = (const float*)d_in[9];
    const float* W2rel  = (const float*)d_in[10];
    const float* b2     = (const float*)d_in[11];
    const float* W2root = (const float*)d_in[12];
    const float* pW2    = (const float*)d_in[13];
    const float* pb2    = (const float*)d_in[14];
    const float* g2     = (const float*)d_in[15];
    const float* be2    = (const float*)d_in[16];
    float* out = (float*)d_out;
    const int* row = ei;
    const int* col = ei + EE;

    cudaFuncSetAttribute(kAB, cudaFuncAttributeMaxDynamicSharedMemorySize, KAB_SMEM_BYTES);
    cudaFuncSetAttribute(k6, cudaFuncAttributeMaxDynamicSharedMemorySize, K6_SMEM_BYTES);

    int nblk = (NN + 63) / 64;  // 782

    kinitA<<<512, 256>>>();
    kmerge0<<<4352, 256>>>(x, dm, row, col, W1rel, W1root, pW1, W2rel, W2root, pW2);
    kAB<<<nblk, 128, KAB_SMEM_BYTES>>>(x, dm, b1, pb1, g1, be1, out + 4);
    kscatter2<<<4096, 256>>>(row, col);
    k5<<<296, 256>>>();
    k6<<<1, 256, K6_SMEM_BYTES>>>(b2, pb2, g2, be2, out, out + 4 + (size_t)NN*C1N);
}